// round 11
// baseline (speedup 1.0000x reference)
#include <cuda_runtime.h>
#include <cuda_fp16.h>
#include <math.h>
#include <stdint.h>

#define B 8
#define D 512
#define L 2048
#define DD (512*512)

#define BLD (8u*2048u*512u)            // 8388608
#define BLL (8ull*2048ull*2048ull)     // 33554432

// single-fp16 operands
__device__ __align__(128) __half gQ[BLD];
__device__ __align__(128) __half gK[BLD];
__device__ __align__(128) __half gVt[BLD];                 // V^T: [b][d][l]
__device__ __align__(128) __half gA[BLL];                  // softmax fp16
__device__ __align__(128) __half gHt[BLD];                 // H^T: [b][l][i]
__device__ __align__(128) __half gW[3*DD];                 // [Wk,Wq,Wv][o][i]

// ---------------------------------------------------------------------------
__device__ __forceinline__ uint32_t smem_u32(const void* p) {
    uint32_t a;
    asm("{ .reg .u64 t; cvta.to.shared.u64 t, %1; cvt.u32.u64 %0, t; }"
        : "=r"(a) : "l"(p));
    return a;
}

__device__ __forceinline__ void ldsm_x4(uint32_t* r, uint32_t addr) {
    asm volatile("ldmatrix.sync.aligned.m8n8.x4.shared.b16 {%0,%1,%2,%3}, [%4];"
        : "=r"(r[0]), "=r"(r[1]), "=r"(r[2]), "=r"(r[3]) : "r"(addr));
}

__device__ __forceinline__ void mma_fp16(float* c, const uint32_t* a, const uint32_t* b) {
    asm volatile(
        "mma.sync.aligned.m16n8k16.row.col.f32.f16.f16.f32 "
        "{%0,%1,%2,%3}, {%4,%5,%6,%7}, {%8,%9}, {%0,%1,%2,%3};"
        : "+f"(c[0]), "+f"(c[1]), "+f"(c[2]), "+f"(c[3])
        : "r"(a[0]), "r"(a[1]), "r"(a[2]), "r"(a[3]), "r"(b[0]), "r"(b[1]));
}

__device__ __forceinline__ void cp16(uint32_t saddr, const void* gaddr) {
    asm volatile("cp.async.cg.shared.global [%0], [%1], 16;"
        :: "r"(saddr), "l"(gaddr) : "memory");
}
#define CP_COMMIT() asm volatile("cp.async.commit_group;" ::: "memory")
#define CP_WAIT1()  asm volatile("cp.async.wait_group 1;" ::: "memory")
#define CP_WAIT0()  asm volatile("cp.async.wait_group 0;" ::: "memory")

__device__ __forceinline__ float elu_f(float x) {
    return x > 0.0f ? x : expm1f(x);
}

// ---------------------------------------------------------------------------
#define ROWB  144                    // 64 halves (128B) + 16B pad
#define TILEB (128 * ROWB)           // 18432
#define STAGEB (2 * TILEB)           // 36864
#define MM_SMEM (3 * STAGEB)         // 110592

// Unified inner chunk: 4 ks-steps, per step 6 ldsm then 16 MMAs.
__device__ __forceinline__ void compute_chunk(
    uint32_t sb, uint32_t offA_l, uint32_t offB_l, int wm, int wn,
    float acc[2][8][4])
{
    #pragma unroll
    for (int ks = 0; ks < 4; ks++) {
        const uint32_t kb = ks * 32;    // 16 halves = 32B per K-step
        uint32_t ah[2][4], bh[4][4];
        const uint32_t abase = sb + offA_l + (uint32_t)(wm * 32) * ROWB + kb;
        ldsm_x4(ah[0], abase);
        ldsm_x4(ah[1], abase + 16 * ROWB);
        const uint32_t bbase = sb + TILEB + offB_l + (uint32_t)(wn * 64) * ROWB + kb;
        ldsm_x4(bh[0], bbase);
        ldsm_x4(bh[1], bbase + 16 * ROWB);
        ldsm_x4(bh[2], bbase + 32 * ROWB);
        ldsm_x4(bh[3], bbase + 48 * ROWB);
        #pragma unroll
        for (int i = 0; i < 2; i++)
            #pragma unroll
            for (int j = 0; j < 8; j++)
                mma_fp16(acc[i][j], ah[i], &bh[j >> 1][(j & 1) * 2]);
    }
}

#define PIPE_BODY(NCH, SRC_A, LD_A, SRC_B, LD_B) \
    ISSUE_CHUNK(0, 0); \
    if ((NCH) > 1) ISSUE_CHUNK(1, 1); \
    int sstage = 0; \
    _Pragma("unroll") \
    for (int ch = 0; ch < (NCH); ch++) { \
        if (ch + 1 < (NCH)) { CP_WAIT1(); } else { CP_WAIT0(); } \
        __syncthreads(); \
        if (ch + 2 < (NCH)) { \
            int nstage = sstage + 2; if (nstage >= 3) nstage -= 3; \
            ISSUE_CHUNK(ch + 2, nstage); \
        } \
        compute_chunk(sbase + sstage * STAGEB, offA_l, offB_l, wm, wn, acc); \
        sstage = (sstage + 1 == 3) ? 0 : sstage + 1; \
    }

#define ISSUE_CHUNK(ch, stg) do { \
        const int _k0 = (ch) * 64; \
        const uint32_t _sb = sbase + (stg) * STAGEB; \
        _Pragma("unroll") \
        for (int j = 0; j < 4; j++) { \
            const int seg = j * 256 + tid; \
            const int r = seg >> 3, c = seg & 7; \
            const uint32_t so = (uint32_t)r * ROWB + c * 16; \
            cp16(_sb + 0*TILEB + so, srcA + (size_t)r*ldA + _k0 + c*8); \
            cp16(_sb + 1*TILEB + so, srcB + (size_t)r*ldB + _k0 + c*8); \
        } \
        CP_COMMIT(); \
    } while (0)

// ---------------------------------------------------------------------------
// Plain fp16 GEMM (EPI0): Cout = scale * Am Bm^T.  grid (M/128, N/128, B)
// ---------------------------------------------------------------------------
template<int NCH>
__global__ __launch_bounds__(256, 2) void mm0_kernel(
    const __half* __restrict__ Am, size_t sA, int ldA_,
    const __half* __restrict__ Bm, size_t sB, int ldB_,
    float* __restrict__ Cout, size_t sC, int ldC, float scale)
{
    extern __shared__ char smem[];
    const uint32_t sbase = smem_u32(smem);
    const int tid = threadIdx.x, wid = tid >> 5, lane = tid & 31;
    const int wm = wid & 3, wn = wid >> 2;
    const int m0 = blockIdx.x * 128, n0 = blockIdx.y * 128, bz = blockIdx.z;
    const int ldA = ldA_, ldB = ldB_;

    const __half* srcA = Am + (size_t)bz * sA + (size_t)m0 * ldA;
    const __half* srcB = Bm + (size_t)bz * sB + (size_t)n0 * ldB;

    float acc[2][8][4];
    #pragma unroll
    for (int i = 0; i < 2; i++)
        #pragma unroll
        for (int j = 0; j < 8; j++)
            #pragma unroll
            for (int t = 0; t < 4; t++) acc[i][j][t] = 0.0f;

    const uint32_t offA_l = (uint32_t)(lane & 15) * ROWB + (lane >> 4) * 16;
    const uint32_t offB_l = (uint32_t)((lane & 7) + ((lane & 16) ? 8 : 0)) * ROWB
                          + ((lane & 8) ? 16 : 0);

    PIPE_BODY(NCH, srcA, ldA, srcB, ldB)

    const int g = lane >> 2, tg = lane & 3;
    float* dst = Cout + (size_t)bz * sC;
    #pragma unroll
    for (int i = 0; i < 2; i++) {
        const int r0 = m0 + wm * 32 + i * 16 + g;
        #pragma unroll
        for (int j = 0; j < 8; j++) {
            const int c = n0 + wn * 64 + j * 8 + tg * 2;
            float2 v0 = make_float2(acc[i][j][0] * scale, acc[i][j][1] * scale);
            float2 v1 = make_float2(acc[i][j][2] * scale, acc[i][j][3] * scale);
            *(float2*)(dst + (size_t)r0 * ldC + c) = v0;
            *(float2*)(dst + (size_t)(r0 + 8) * ldC + c) = v1;
        }
    }
}

// ---------------------------------------------------------------------------
// Unified projection kernel: grid (16, 4, 3*B), z%3: 0=K, 1=Q, 2=V^T.
//  w<2 : out[l][o] = elu(Ht W^T + b[col]),  m0 = x*128 (l), n0 = y*128 (o)
//  w==2: out[o][l] = elu(Wv Ht^T + b[row]), m0 = y*128 (o), n0 = x*128 (l)
// ---------------------------------------------------------------------------
__global__ __launch_bounds__(256, 2) void proj_kernel(
    const float* __restrict__ bk, const float* __restrict__ bq,
    const float* __restrict__ bv)
{
    extern __shared__ char smem[];
    const uint32_t sbase = smem_u32(smem);
    const int tid = threadIdx.x, wid = tid >> 5, lane = tid & 31;
    const int wm = wid & 3, wn = wid >> 2;
    const int bz = blockIdx.z / 3, w = blockIdx.z % 3;
    const bool isv = (w == 2);
    const int m0 = (isv ? blockIdx.y : blockIdx.x) * 128;
    const int n0 = (isv ? blockIdx.x : blockIdx.y) * 128;
    const int ldA = D, ldB = D;

    const __half* srcA = isv ? (gW + 2 * DD + (size_t)m0 * D)
                             : (gHt + (size_t)bz * L * D + (size_t)m0 * D);
    const __half* srcB = isv ? (gHt + (size_t)bz * L * D + (size_t)n0 * D)
                             : (gW + (size_t)w * DD + (size_t)n0 * D);

    float acc[2][8][4];
    #pragma unroll
    for (int i = 0; i < 2; i++)
        #pragma unroll
        for (int j = 0; j < 8; j++)
            #pragma unroll
            for (int t = 0; t < 4; t++) acc[i][j][t] = 0.0f;

    const uint32_t offA_l = (uint32_t)(lane & 15) * ROWB + (lane >> 4) * 16;
    const uint32_t offB_l = (uint32_t)((lane & 7) + ((lane & 16) ? 8 : 0)) * ROWB
                          + ((lane & 8) ? 16 : 0);

    PIPE_BODY(8, srcA, ldA, srcB, ldB)

    const int g = lane >> 2, tg = lane & 3;
    const float* bias = isv ? bv : (w ? bq : bk);
    __half* oh = isv ? (gVt + (size_t)bz * D * L)
                     : ((w ? gQ : gK) + (size_t)bz * L * D);
    const int ldC = isv ? L : D;
    #pragma unroll
    for (int i = 0; i < 2; i++) {
        const int r0 = m0 + wm * 32 + i * 16 + g;
        #pragma unroll
        for (int j = 0; j < 8; j++) {
            const int c = n0 + wn * 64 + j * 8 + tg * 2;
            float f00, f01, f10, f11;
            if (isv) {
                float b0 = bias[r0], b1 = bias[r0 + 8];
                f00 = elu_f(acc[i][j][0] + b0);
                f01 = elu_f(acc[i][j][1] + b0);
                f10 = elu_f(acc[i][j][2] + b1);
                f11 = elu_f(acc[i][j][3] + b1);
            } else {
                float b0 = bias[c], b1 = bias[c + 1];
                f00 = elu_f(acc[i][j][0] + b0);
                f01 = elu_f(acc[i][j][1] + b1);
                f10 = elu_f(acc[i][j][2] + b0);
                f11 = elu_f(acc[i][j][3] + b1);
            }
            *(__half2*)(oh + (size_t)r0 * ldC + c) = __floats2half2_rn(f00, f01);
            *(__half2*)(oh + (size_t)(r0 + 8) * ldC + c) = __floats2half2_rn(f10, f11);
        }
    }
}

// ---------------------------------------------------------------------------
// H^T: H[b][i][l] fp32 -> gHt [b][l][i] fp16
// ---------------------------------------------------------------------------
__global__ __launch_bounds__(256) void hsplit_kernel(const float* __restrict__ H)
{
    __shared__ float t[32][33];
    const int b = blockIdx.z;
    const int l0 = blockIdx.x * 32, i0 = blockIdx.y * 32;
    const int tx = threadIdx.x & 31, ty = threadIdx.x >> 5;

    const float* Hb = H + ((size_t)b * D + i0) * L + l0;
    #pragma unroll
    for (int r = 0; r < 4; r++)
        t[ty + 8 * r][tx] = Hb[(size_t)(ty + 8 * r) * L + tx];
    __syncthreads();

    #pragma unroll
    for (int r = 0; r < 4; r++) {
        float v = t[tx][ty + 8 * r];
        size_t idx = ((size_t)b * L + l0 + ty + 8 * r) * D + i0 + tx;
        gHt[idx] = __float2half_rn(v);
    }
}

// ---------------------------------------------------------------------------
// W convert: [Wk, Wq, Wv] fp32 -> gW fp16
// ---------------------------------------------------------------------------
__global__ __launch_bounds__(256) void wsplit_kernel(
    const float* __restrict__ Wk, const float* __restrict__ Wq,
    const float* __restrict__ Wv)
{
    int idx = blockIdx.x * 256 + threadIdx.x;
    if (idx >= 3 * DD) return;
    int which = idx / DD, off = idx % DD;
    const float* W = (which == 0) ? Wk : (which == 1) ? Wq : Wv;
    gW[idx] = __float2half_rn(W[off]);
}

// ---------------------------------------------------------------------------
// Row softmax (L=2048): warp-shuffle reductions, float4 I/O, __expf.
// ---------------------------------------------------------------------------
__global__ __launch_bounds__(256) void softmax_kernel(float* __restrict__ A)
{
    __shared__ float red[8];
    const size_t base = (size_t)blockIdx.x * L;
    float4* rowv = (float4*)(A + base);
    const int tid = threadIdx.x, lane = tid & 31, wid = tid >> 5;

    float4 v[2];
    v[0] = rowv[tid];
    v[1] = rowv[tid + 256];

    float m = fmaxf(fmaxf(fmaxf(v[0].x, v[0].y), fmaxf(v[0].z, v[0].w)),
                    fmaxf(fmaxf(v[1].x, v[1].y), fmaxf(v[1].z, v[1].w)));
    #pragma unroll
    for (int s = 16; s > 0; s >>= 1)
        m = fmaxf(m, __shfl_xor_sync(0xFFFFFFFFu, m, s));
    if (lane == 0) red[wid] = m;
    __syncthreads();
    {
        float t = red[lane & 7];
        #pragma unroll
        for (int s = 4; s > 0; s >>= 1)
            t = fmaxf(t, __shfl_xor_sync(0xFFFFFFFFu, t, s));
        m = t;
    }

    float sum = 0.0f;
    #pragma unroll
    for (int q = 0; q < 2; q++) {
        v[q].x = __expf(v[q].x - m);
        v[q].y = __expf(v[q].y - m);
        v[q].z = __expf(v[q].z - m);
        v[q].w = __expf(v[q].w - m);
        sum += (v[q].x + v[q].y) + (v[q].z + v[q].w);
    }
    #pragma unroll
    for (int s = 16; s > 0; s >>= 1)
        sum += __shfl_xor_sync(0xFFFFFFFFu, sum, s);
    __syncthreads();
    if (lane == 0) red[wid] = sum;
    __syncthreads();
    {
        float t = red[lane & 7];
        #pragma unroll
        for (int s = 4; s > 0; s >>= 1)
            t += __shfl_xor_sync(0xFFFFFFFFu, t, s);
        sum = t;
    }
    const float inv = 1.0f / sum;

    __half2* ap = (__half2*)(gA + base);
    #pragma unroll
    for (int q = 0; q < 2; q++) {
        float4 a;
        a.x = v[q].x * inv; a.y = v[q].y * inv;
        a.z = v[q].z * inv; a.w = v[q].w * inv;
        rowv[tid + q * 256] = a;
        ap[(tid + q * 256) * 2]     = __floats2half2_rn(a.x, a.y);
        ap[(tid + q * 256) * 2 + 1] = __floats2half2_rn(a.z, a.w);
    }
}

// ---------------------------------------------------------------------------
extern "C" void kernel_launch(void* const* d_in, const int* in_sizes, int n_in,
                              void* d_out, int out_size)
{
    const float* H  = (const float*)d_in[0];
    const float* Wk = (const float*)d_in[1];
    const float* bk = (const float*)d_in[2];
    const float* Wq = (const float*)d_in[3];
    const float* bq = (const float*)d_in[4];
    const float* Wv = (const float*)d_in[5];
    const float* bv = (const float*)d_in[6];

    float* C_out = (float*)d_out;                    // [B, L, D]
    float* A_out = C_out + (size_t)B * L * D;        // [B, L, L]

    cudaFuncSetAttribute(mm0_kernel<8>,  cudaFuncAttributeMaxDynamicSharedMemorySize, MM_SMEM);
    cudaFuncSetAttribute(mm0_kernel<32>, cudaFuncAttributeMaxDynamicSharedMemorySize, MM_SMEM);
    cudaFuncSetAttribute(proj_kernel,    cudaFuncAttributeMaxDynamicSharedMemorySize, MM_SMEM);

    __half *q, *k, *vt, *a;
    cudaGetSymbolAddress((void**)&q, gQ);
    cudaGetSymbolAddress((void**)&k, gK);
    cudaGetSymbolAddress((void**)&vt, gVt);
    cudaGetSymbolAddress((void**)&a, gA);

    // 0) converts
    wsplit_kernel<<<(3 * DD + 255) / 256, 256>>>(Wk, Wq, Wv);
    {
        dim3 grid(L / 32, D / 32, B);
        hsplit_kernel<<<grid, 256>>>(H);
    }

    // 1) all three projections in one launch
    {
        dim3 grid(16, 4, 3 * B);
        proj_kernel<<<grid, 256, MM_SMEM>>>(bk, bq, bv);
    }

    // 2) E = scale * Q K^T
    {
        dim3 grid(L / 128, L / 128, B);
        mm0_kernel<8><<<grid, 256, MM_SMEM>>>(
            q, (size_t)L * D, D,
            k, (size_t)L * D, D,
            A_out, (size_t)L * L, L, 0.044194173824159216f);
    }

    // 3) softmax rows + fp16 A
    softmax_kernel<<<B * L, 256>>>(A_out);

    // 4) C = A V
    {
        dim3 grid(L / 128, D / 128, B);
        mm0_kernel<32><<<grid, 256, MM_SMEM>>>(
            a, (size_t)L * L, L,
            vt, (size_t)D * L, L,
            C_out, (size_t)L * D, D, 1.0f);
    }
}

// round 12
// speedup vs baseline: 1.0256x; 1.0256x over previous
#include <cuda_runtime.h>
#include <cuda_fp16.h>
#include <math.h>
#include <stdint.h>

#define B 8
#define D 512
#define L 2048
#define DD (512*512)

#define BLD (8u*2048u*512u)            // 8388608
#define BLL (8ull*2048ull*2048ull)     // 33554432

// single-fp16 operands
__device__ __align__(128) __half gQ[BLD];
__device__ __align__(128) __half gK[BLD];
__device__ __align__(128) __half gVt[BLD];                 // V^T: [b][d][l]
__device__ __align__(128) __half gA[BLL];                  // softmax fp16
__device__ __align__(128) __half gHt[BLD];                 // H^T: [b][l][i]
__device__ __align__(128) __half gW[3*DD];                 // [Wk,Wq,Wv][o][i]

// ---------------------------------------------------------------------------
__device__ __forceinline__ uint32_t smem_u32(const void* p) {
    uint32_t a;
    asm("{ .reg .u64 t; cvta.to.shared.u64 t, %1; cvt.u32.u64 %0, t; }"
        : "=r"(a) : "l"(p));
    return a;
}

__device__ __forceinline__ void ldsm_x4(uint32_t* r, uint32_t addr) {
    asm volatile("ldmatrix.sync.aligned.m8n8.x4.shared.b16 {%0,%1,%2,%3}, [%4];"
        : "=r"(r[0]), "=r"(r[1]), "=r"(r[2]), "=r"(r[3]) : "r"(addr));
}

__device__ __forceinline__ void mma_fp16(float* c, const uint32_t* a, const uint32_t* b) {
    asm volatile(
        "mma.sync.aligned.m16n8k16.row.col.f32.f16.f16.f32 "
        "{%0,%1,%2,%3}, {%4,%5,%6,%7}, {%8,%9}, {%0,%1,%2,%3};"
        : "+f"(c[0]), "+f"(c[1]), "+f"(c[2]), "+f"(c[3])
        : "r"(a[0]), "r"(a[1]), "r"(a[2]), "r"(a[3]), "r"(b[0]), "r"(b[1]));
}

__device__ __forceinline__ void cp16(uint32_t saddr, const void* gaddr) {
    asm volatile("cp.async.cg.shared.global [%0], [%1], 16;"
        :: "r"(saddr), "l"(gaddr) : "memory");
}
#define CP_COMMIT() asm volatile("cp.async.commit_group;" ::: "memory")
#define CP_WAIT1()  asm volatile("cp.async.wait_group 1;" ::: "memory")
#define CP_WAIT0()  asm volatile("cp.async.wait_group 0;" ::: "memory")

__device__ __forceinline__ float elu_f(float x) {
    return x > 0.0f ? x : expm1f(x);
}

// ---------------------------------------------------------------------------
#define ROWB  144                    // 64 halves (128B) + 16B pad
#define TILEB (128 * ROWB)           // 18432
#define STAGEB (2 * TILEB)           // 36864
#define MM_SMEM (3 * STAGEB)         // 110592

// Unified inner chunk: 4 ks-steps, per step 6 ldsm then 16 back-to-back MMAs.
__device__ __forceinline__ void compute_chunk(
    uint32_t sb, uint32_t offA_l, uint32_t offB_l, int wm, int wn,
    float acc[2][8][4])
{
    #pragma unroll
    for (int ks = 0; ks < 4; ks++) {
        const uint32_t kb = ks * 32;    // 16 halves = 32B per K-step
        uint32_t ah[2][4], bh[4][4];
        const uint32_t abase = sb + offA_l + (uint32_t)(wm * 32) * ROWB + kb;
        ldsm_x4(ah[0], abase);
        ldsm_x4(ah[1], abase + 16 * ROWB);
        const uint32_t bbase = sb + TILEB + offB_l + (uint32_t)(wn * 64) * ROWB + kb;
        ldsm_x4(bh[0], bbase);
        ldsm_x4(bh[1], bbase + 16 * ROWB);
        ldsm_x4(bh[2], bbase + 32 * ROWB);
        ldsm_x4(bh[3], bbase + 48 * ROWB);
        #pragma unroll
        for (int i = 0; i < 2; i++)
            #pragma unroll
            for (int j = 0; j < 8; j++)
                mma_fp16(acc[i][j], ah[i], &bh[j >> 1][(j & 1) * 2]);
    }
}

#define ISSUE_CHUNK(ch, stg) do { \
        const int _k0 = (ch) * 64; \
        const uint32_t _sb = sbase + (stg) * STAGEB; \
        _Pragma("unroll") \
        for (int j = 0; j < 4; j++) { \
            const int seg = j * 256 + tid; \
            const int r = seg >> 3, c = seg & 7; \
            const uint32_t so = (uint32_t)r * ROWB + c * 16; \
            cp16(_sb + 0*TILEB + so, srcA + (size_t)r*ldA + _k0 + c*8); \
            cp16(_sb + 1*TILEB + so, srcB + (size_t)r*ldB + _k0 + c*8); \
        } \
        CP_COMMIT(); \
    } while (0)

#define PIPE_BODY(NCH) \
    ISSUE_CHUNK(0, 0); \
    if ((NCH) > 1) ISSUE_CHUNK(1, 1); \
    int sstage = 0; \
    _Pragma("unroll") \
    for (int ch = 0; ch < (NCH); ch++) { \
        if (ch + 1 < (NCH)) { CP_WAIT1(); } else { CP_WAIT0(); } \
        __syncthreads(); \
        if (ch + 2 < (NCH)) { \
            int nstage = sstage + 2; if (nstage >= 3) nstage -= 3; \
            ISSUE_CHUNK(ch + 2, nstage); \
        } \
        compute_chunk(sbase + sstage * STAGEB, offA_l, offB_l, wm, wn, acc); \
        sstage = (sstage + 1 == 3) ? 0 : sstage + 1; \
    }

// ---------------------------------------------------------------------------
// fp16 GEMM: acc[m,n] = sum_k A[m,k] * Bm[n,k]
// CTA tile 128x128, K-chunk 64, NCH chunks. 8 warps, 32x64 each. 2 CTAs/SM.
// MERGED: grid.z = 2*B, z&1 selects {B-matrix, bias, output} (K/Q proj merge).
// EPI 0: Cout = scale*acc (fp32)
// EPI 2: fp16 of elu(acc + bias[row])
// EPI 3: fp16 of elu(acc + bias[col])
// ---------------------------------------------------------------------------
template<int EPI, int NCH, int MERGED>
__global__ __launch_bounds__(256, 2) void mm_kernel(
    const __half* __restrict__ Am, size_t sA, int ldA_,
    const __half* __restrict__ Bm, size_t sB, int ldB_,
    float* __restrict__ Cout,
    __half* __restrict__ O0, __half* __restrict__ O1,
    const float* __restrict__ bias0, const float* __restrict__ bias1,
    size_t sC, int ldC, float scale)
{
    extern __shared__ char smem[];
    const uint32_t sbase = smem_u32(smem);
    const int tid = threadIdx.x, wid = tid >> 5, lane = tid & 31;
    const int wm = wid & 3, wn = wid >> 2;
    const int m0 = blockIdx.x * 128, n0 = blockIdx.y * 128;
    const int bz = MERGED ? (int)(blockIdx.z >> 1) : (int)blockIdx.z;
    const int which = MERGED ? (int)(blockIdx.z & 1) : 0;
    const int ldA = ldA_, ldB = ldB_;

    const __half* srcA = Am + (size_t)bz * sA + (size_t)m0 * ldA;
    const __half* srcB = Bm + (size_t)(MERGED ? which : bz) * sB
                            + (size_t)n0 * ldB;

    float acc[2][8][4];
    #pragma unroll
    for (int i = 0; i < 2; i++)
        #pragma unroll
        for (int j = 0; j < 8; j++)
            #pragma unroll
            for (int t = 0; t < 4; t++) acc[i][j][t] = 0.0f;

    const uint32_t offA_l = (uint32_t)(lane & 15) * ROWB + (lane >> 4) * 16;
    const uint32_t offB_l = (uint32_t)((lane & 7) + ((lane & 16) ? 8 : 0)) * ROWB
                          + ((lane & 8) ? 16 : 0);

    PIPE_BODY(NCH)

    // epilogue
    const int g = lane >> 2, tg = lane & 3;
    const float* bias = (MERGED && which) ? bias1 : bias0;
    __half* Oh = (MERGED && which) ? O1 : O0;
    #pragma unroll
    for (int i = 0; i < 2; i++) {
        const int r0 = m0 + wm * 32 + i * 16 + g;
        #pragma unroll
        for (int j = 0; j < 8; j++) {
            const int c = n0 + wn * 64 + j * 8 + tg * 2;
            if (EPI == 0) {
                float* dst = Cout + (size_t)bz * sC;
                float2 v0 = make_float2(acc[i][j][0] * scale, acc[i][j][1] * scale);
                float2 v1 = make_float2(acc[i][j][2] * scale, acc[i][j][3] * scale);
                *(float2*)(dst + (size_t)r0 * ldC + c) = v0;
                *(float2*)(dst + (size_t)(r0 + 8) * ldC + c) = v1;
            } else {
                __half* oh = Oh + (size_t)bz * sC;
                float f00, f01, f10, f11;
                if (EPI == 2) {
                    float b0 = bias[r0], b1 = bias[r0 + 8];
                    f00 = elu_f(acc[i][j][0] + b0);
                    f01 = elu_f(acc[i][j][1] + b0);
                    f10 = elu_f(acc[i][j][2] + b1);
                    f11 = elu_f(acc[i][j][3] + b1);
                } else {
                    float b0 = bias[c], b1 = bias[c + 1];
                    f00 = elu_f(acc[i][j][0] + b0);
                    f01 = elu_f(acc[i][j][1] + b1);
                    f10 = elu_f(acc[i][j][2] + b0);
                    f11 = elu_f(acc[i][j][3] + b1);
                }
                *(__half2*)(oh + (size_t)r0 * ldC + c) = __floats2half2_rn(f00, f01);
                *(__half2*)(oh + (size_t)(r0 + 8) * ldC + c) = __floats2half2_rn(f10, f11);
            }
        }
    }
}

// ---------------------------------------------------------------------------
// H^T: H[b][i][l] fp32 -> gHt [b][l][i] fp16
// ---------------------------------------------------------------------------
__global__ __launch_bounds__(256) void hsplit_kernel(const float* __restrict__ H)
{
    __shared__ float t[32][33];
    const int b = blockIdx.z;
    const int l0 = blockIdx.x * 32, i0 = blockIdx.y * 32;
    const int tx = threadIdx.x & 31, ty = threadIdx.x >> 5;

    const float* Hb = H + ((size_t)b * D + i0) * L + l0;
    #pragma unroll
    for (int r = 0; r < 4; r++)
        t[ty + 8 * r][tx] = Hb[(size_t)(ty + 8 * r) * L + tx];
    __syncthreads();

    #pragma unroll
    for (int r = 0; r < 4; r++) {
        float v = t[tx][ty + 8 * r];
        size_t idx = ((size_t)b * L + l0 + ty + 8 * r) * D + i0 + tx;
        gHt[idx] = __float2half_rn(v);
    }
}

// ---------------------------------------------------------------------------
// W convert: [Wk, Wq, Wv] fp32 -> gW fp16
// ---------------------------------------------------------------------------
__global__ __launch_bounds__(256) void wsplit_kernel(
    const float* __restrict__ Wk, const float* __restrict__ Wq,
    const float* __restrict__ Wv)
{
    int idx = blockIdx.x * 256 + threadIdx.x;
    if (idx >= 3 * DD) return;
    int which = idx / DD, off = idx % DD;
    const float* W = (which == 0) ? Wk : (which == 1) ? Wq : Wv;
    gW[idx] = __float2half_rn(W[off]);
}

// ---------------------------------------------------------------------------
// Row softmax (L=2048): warp-shuffle reductions, float4 I/O, __expf.
// ---------------------------------------------------------------------------
__global__ __launch_bounds__(256) void softmax_kernel(float* __restrict__ A)
{
    __shared__ float red[8];
    const size_t base = (size_t)blockIdx.x * L;
    float4* rowv = (float4*)(A + base);
    const int tid = threadIdx.x, lane = tid & 31, wid = tid >> 5;

    float4 v[2];
    v[0] = rowv[tid];
    v[1] = rowv[tid + 256];

    float m = fmaxf(fmaxf(fmaxf(v[0].x, v[0].y), fmaxf(v[0].z, v[0].w)),
                    fmaxf(fmaxf(v[1].x, v[1].y), fmaxf(v[1].z, v[1].w)));
    #pragma unroll
    for (int s = 16; s > 0; s >>= 1)
        m = fmaxf(m, __shfl_xor_sync(0xFFFFFFFFu, m, s));
    if (lane == 0) red[wid] = m;
    __syncthreads();
    {
        float t = red[lane & 7];
        #pragma unroll
        for (int s = 4; s > 0; s >>= 1)
            t = fmaxf(t, __shfl_xor_sync(0xFFFFFFFFu, t, s));
        m = t;
    }

    float sum = 0.0f;
    #pragma unroll
    for (int q = 0; q < 2; q++) {
        v[q].x = __expf(v[q].x - m);
        v[q].y = __expf(v[q].y - m);
        v[q].z = __expf(v[q].z - m);
        v[q].w = __expf(v[q].w - m);
        sum += (v[q].x + v[q].y) + (v[q].z + v[q].w);
    }
    #pragma unroll
    for (int s = 16; s > 0; s >>= 1)
        sum += __shfl_xor_sync(0xFFFFFFFFu, sum, s);
    __syncthreads();
    if (lane == 0) red[wid] = sum;
    __syncthreads();
    {
        float t = red[lane & 7];
        #pragma unroll
        for (int s = 4; s > 0; s >>= 1)
            t += __shfl_xor_sync(0xFFFFFFFFu, t, s);
        sum = t;
    }
    const float inv = 1.0f / sum;

    __half2* ap = (__half2*)(gA + base);
    #pragma unroll
    for (int q = 0; q < 2; q++) {
        float4 a;
        a.x = v[q].x * inv; a.y = v[q].y * inv;
        a.z = v[q].z * inv; a.w = v[q].w * inv;
        rowv[tid + q * 256] = a;
        ap[(tid + q * 256) * 2]     = __floats2half2_rn(a.x, a.y);
        ap[(tid + q * 256) * 2 + 1] = __floats2half2_rn(a.z, a.w);
    }
}

// ---------------------------------------------------------------------------
extern "C" void kernel_launch(void* const* d_in, const int* in_sizes, int n_in,
                              void* d_out, int out_size)
{
    const float* H  = (const float*)d_in[0];
    const float* Wk = (const float*)d_in[1];
    const float* bk = (const float*)d_in[2];
    const float* Wq = (const float*)d_in[3];
    const float* bq = (const float*)d_in[4];
    const float* Wv = (const float*)d_in[5];
    const float* bv = (const float*)d_in[6];

    float* C_out = (float*)d_out;                    // [B, L, D]
    float* A_out = C_out + (size_t)B * L * D;        // [B, L, L]

    cudaFuncSetAttribute(mm_kernel<0,8,0>,  cudaFuncAttributeMaxDynamicSharedMemorySize, MM_SMEM);
    cudaFuncSetAttribute(mm_kernel<0,32,0>, cudaFuncAttributeMaxDynamicSharedMemorySize, MM_SMEM);
    cudaFuncSetAttribute(mm_kernel<2,8,0>,  cudaFuncAttributeMaxDynamicSharedMemorySize, MM_SMEM);
    cudaFuncSetAttribute(mm_kernel<3,8,1>,  cudaFuncAttributeMaxDynamicSharedMemorySize, MM_SMEM);

    __half *q, *k, *vt, *a, *ht, *w;
    cudaGetSymbolAddress((void**)&q, gQ);
    cudaGetSymbolAddress((void**)&k, gK);
    cudaGetSymbolAddress((void**)&vt, gVt);
    cudaGetSymbolAddress((void**)&a, gA);
    cudaGetSymbolAddress((void**)&ht, gHt);
    cudaGetSymbolAddress((void**)&w, gW);

    // 0) converts
    wsplit_kernel<<<(3 * DD + 255) / 256, 256>>>(Wk, Wq, Wv);
    {
        dim3 grid(L / 32, D / 32, B);
        hsplit_kernel<<<grid, 256>>>(H);
    }

    // 1) merged K(z even) / Q(z odd) projection: elu(Ht W^T + b) -> [l][o] fp16
    {
        dim3 grid(L / 128, D / 128, 2 * B);
        mm_kernel<3,8,1><<<grid, 256, MM_SMEM>>>(
            ht, (size_t)L * D, D,
            w, (size_t)DD, D,            // which-stride = DD (Wk then Wq)
            nullptr, k, q, bk, bq,
            (size_t)L * D, D, 1.0f);
    }
    // V^T = elu(Wv Ht^T + bv[row]) -> [o][l] fp16
    {
        dim3 grid(D / 128, L / 128, B);
        mm_kernel<2,8,0><<<grid, 256, MM_SMEM>>>(
            w + 2 * DD, 0, D,
            ht, (size_t)L * D, D,
            nullptr, vt, nullptr, bv, nullptr,
            (size_t)D * L, L, 1.0f);
    }

    // 2) E = scale * Q K^T
    {
        dim3 grid(L / 128, L / 128, B);
        mm_kernel<0,8,0><<<grid, 256, MM_SMEM>>>(
            q, (size_t)L * D, D,
            k, (size_t)L * D, D,
            A_out, nullptr, nullptr, nullptr, nullptr,
            (size_t)L * L, L, 0.044194173824159216f);
    }

    // 3) softmax rows + fp16 A
    softmax_kernel<<<B * L, 256>>>(A_out);

    // 4) C = A V
    {
        dim3 grid(L / 128, D / 128, B);
        mm_kernel<0,32,0><<<grid, 256, MM_SMEM>>>(
            a, (size_t)L * L, L,
            vt, (size_t)D * L, L,
            C_out, nullptr, nullptr, nullptr, nullptr,
            (size_t)L * D, D, 1.0f);
    }
}